// round 3
// baseline (speedup 1.0000x reference)
#include <cuda_runtime.h>

#define B_ 8
#define C_ 512
#define N_ 4096
#define H_ 8
#define D_ 64

// ---- scratch (device globals: allocation-free) ----
__device__ float g_q[(size_t)B_ * C_ * N_];          //  64 MB
__device__ float g_kv[(size_t)B_ * 2 * C_ * N_];     // 128 MB
__device__ float g_attn[(size_t)B_ * H_ * D_ * D_];  //   1 MB
__device__ float g_o[(size_t)B_ * C_ * N_];          //  64 MB

// Buffer selectors so kernel_launch never needs cudaGetSymbolAddress:
// 0 = external pointer (passed in), 1 = g_q, 2 = g_kv, 3 = g_o
__device__ __forceinline__ float* resolve_buf(int sel, float* ext) {
    switch (sel) {
        case 1: return g_q;
        case 2: return g_kv;
        case 3: return g_o;
        default: return ext;
    }
}
__device__ __forceinline__ const float* resolve_buf_c(int sel, const float* ext) {
    switch (sel) {
        case 1: return g_q;
        case 2: return g_kv;
        case 3: return g_o;
        default: return ext;
    }
}

// ============================================================================
// GEMM: Cp[b] = A(MxK) * Bp[b](KxN) (+ bias per row). 128x128x16 tile,
// 256 threads, 8x8 per thread, float4 global loads, A staged transposed,
// software-pipelined smem->reg loads in the kk loop.
// ============================================================================
__global__ __launch_bounds__(256) void sgemm_kernel(
    const float* __restrict__ A,
    const float* __restrict__ Bext, int bSel,
    float* __restrict__ Cext, int cSel,
    const float* __restrict__ bias,
    int M, int N, int K, long sB, long sC)
{
    const float* Bm = resolve_buf_c(bSel, Bext);
    float*       Cm = resolve_buf(cSel, Cext);
    const float* Bp = Bm + (long)blockIdx.z * sB;
    float*       Cp = Cm + (long)blockIdx.z * sC;
    const int m0 = blockIdx.y * 128;
    const int n0 = blockIdx.x * 128;

    __shared__ float As[16][128];
    __shared__ float Bs[16][128];

    const int tid = threadIdx.x;
    const int tx  = tid & 15;   // n-group
    const int ty  = tid >> 4;   // m-group

    float acc[8][8] = {};

    for (int k0 = 0; k0 < K; k0 += 16) {
        // A tile: 128 rows x 16 k = 512 float4; store transposed As[k][m]
        #pragma unroll
        for (int l = 0; l < 2; l++) {
            int f  = tid + l * 256;
            int r  = f >> 2, c4 = f & 3;
            float4 v = *(const float4*)(A + (long)(m0 + r) * K + k0 + c4 * 4);
            As[c4 * 4 + 0][r] = v.x;
            As[c4 * 4 + 1][r] = v.y;
            As[c4 * 4 + 2][r] = v.z;
            As[c4 * 4 + 3][r] = v.w;
        }
        // B tile: 16 k-rows x 128 n = 512 float4, direct
        #pragma unroll
        for (int l = 0; l < 2; l++) {
            int f  = tid + l * 256;
            int r  = f >> 5, c4 = f & 31;
            *(float4*)&Bs[r][c4 * 4] =
                *(const float4*)(Bp + (long)(k0 + r) * N + n0 + c4 * 4);
        }
        __syncthreads();

        // software-pipelined: fetch regs for kk+1 while FMAs for kk run
        float a[2][8], b[2][8];
        *(float4*)&a[0][0] = *(const float4*)&As[0][ty * 4];
        *(float4*)&a[0][4] = *(const float4*)&As[0][64 + ty * 4];
        *(float4*)&b[0][0] = *(const float4*)&Bs[0][tx * 4];
        *(float4*)&b[0][4] = *(const float4*)&Bs[0][64 + tx * 4];

        #pragma unroll
        for (int kk = 0; kk < 16; kk++) {
            int cur = kk & 1, nxt = cur ^ 1;
            if (kk < 15) {
                *(float4*)&a[nxt][0] = *(const float4*)&As[kk + 1][ty * 4];
                *(float4*)&a[nxt][4] = *(const float4*)&As[kk + 1][64 + ty * 4];
                *(float4*)&b[nxt][0] = *(const float4*)&Bs[kk + 1][tx * 4];
                *(float4*)&b[nxt][4] = *(const float4*)&Bs[kk + 1][64 + tx * 4];
            }
            #pragma unroll
            for (int i = 0; i < 8; i++)
                #pragma unroll
                for (int j = 0; j < 8; j++)
                    acc[i][j] += a[cur][i] * b[cur][j];
        }
        __syncthreads();
    }

    #pragma unroll
    for (int i = 0; i < 8; i++) {
        int m = m0 + (i < 4 ? ty * 4 + i : 64 + ty * 4 + (i - 4));
        float bv = bias ? bias[m] : 0.0f;
        #pragma unroll
        for (int jq = 0; jq < 2; jq++) {
            int n = n0 + (jq == 0 ? tx * 4 : 64 + tx * 4);
            float4 o;
            o.x = acc[i][jq * 4 + 0] + bv;
            o.y = acc[i][jq * 4 + 1] + bv;
            o.z = acc[i][jq * 4 + 2] + bv;
            o.w = acc[i][jq * 4 + 3] + bv;
            *(float4*)(Cp + (long)m * N + n) = o;
        }
    }
}

// ============================================================================
// dots[b,h] = scale * q_h (64 x 4096) @ k_h^T, then row softmax -> g_attn.
// One CTA per (b,h); K-dim (n=4096) streamed through smem in 64-chunks,
// staged transposed so the inner product reads qs[n][i] / ks[n][j].
// ============================================================================
__global__ __launch_bounds__(256) void scores_softmax_kernel()
{
    const int bh = blockIdx.x;           // 0..63
    const int b  = bh >> 3, h = bh & 7;
    const float* q = g_q  + (long)b * C_ * N_     + (long)h * D_ * N_;
    const float* k = g_kv + (long)b * 2 * C_ * N_ + (long)h * D_ * N_;

    __shared__ float qs[64][65];
    __shared__ float ks[64][65];

    const int tid = threadIdx.x;
    const int i0  = (tid >> 4) * 4;
    const int j0  = (tid & 15) * 4;

    float acc[4][4] = {};

    for (int n0 = 0; n0 < N_; n0 += 64) {
        #pragma unroll
        for (int l = 0; l < 4; l++) {
            int f = tid + l * 256;        // 1024 float4: 64 rows x 16
            int i = f >> 4, n4 = f & 15;
            float4 v = *(const float4*)(q + (long)i * N_ + n0 + n4 * 4);
            qs[n4 * 4 + 0][i] = v.x; qs[n4 * 4 + 1][i] = v.y;
            qs[n4 * 4 + 2][i] = v.z; qs[n4 * 4 + 3][i] = v.w;
            float4 w = *(const float4*)(k + (long)i * N_ + n0 + n4 * 4);
            ks[n4 * 4 + 0][i] = w.x; ks[n4 * 4 + 1][i] = w.y;
            ks[n4 * 4 + 2][i] = w.z; ks[n4 * 4 + 3][i] = w.w;
        }
        __syncthreads();

        #pragma unroll 8
        for (int nn = 0; nn < 64; nn++) {
            float qa[4], ka[4];
            #pragma unroll
            for (int ii = 0; ii < 4; ii++) qa[ii] = qs[nn][i0 + ii];
            #pragma unroll
            for (int jj = 0; jj < 4; jj++) ka[jj] = ks[nn][j0 + jj];
            #pragma unroll
            for (int ii = 0; ii < 4; ii++)
                #pragma unroll
                for (int jj = 0; jj < 4; jj++)
                    acc[ii][jj] += qa[ii] * ka[jj];
        }
        __syncthreads();
    }

    const float scale = 0.125f;  // 64^-0.5
    // stash scaled dots (reuse qs as ds[i][j])
    #pragma unroll
    for (int ii = 0; ii < 4; ii++)
        #pragma unroll
        for (int jj = 0; jj < 4; jj++)
            qs[i0 + ii][j0 + jj] = acc[ii][jj] * scale;
    __syncthreads();

    if (tid < 64) {
        float row[64];
        float mx = -1e30f;
        #pragma unroll
        for (int j = 0; j < 64; j++) { row[j] = qs[tid][j]; mx = fmaxf(mx, row[j]); }
        float s = 0.0f;
        #pragma unroll
        for (int j = 0; j < 64; j++) { row[j] = __expf(row[j] - mx); s += row[j]; }
        float inv = 1.0f / s;
        float* out = g_attn + (long)bh * D_ * D_ + (long)tid * D_;
        #pragma unroll
        for (int j = 0; j < 64; j++) out[j] = row[j] * inv;
    }
}

// ============================================================================
// o[b,h] = attn (64x64) @ v_h (64 x 4096). attn resident in smem (broadcast
// reads), v column held in registers; grid = (n/128, b*h).
// ============================================================================
__global__ __launch_bounds__(256) void apply_v_kernel()
{
    const int bh = blockIdx.y;
    const int b  = bh >> 3, h = bh & 7;
    const float* attn = g_attn + (long)bh * D_ * D_;
    const float* v    = g_kv + (long)b * 2 * C_ * N_ + (long)(C_ + h * D_) * N_;
    float*       o    = g_o  + (long)b * C_ * N_     + (long)h * D_ * N_;

    __shared__ float as[64][64];
    const int tid = threadIdx.x;
    #pragma unroll
    for (int l = 0; l < 4; l++) {
        int f = tid + l * 256;  // 1024 float4
        *(float4*)&as[f >> 4][(f & 15) * 4] = *(const float4*)(attn + f * 4);
    }
    __syncthreads();

    const int n  = blockIdx.x * 128 + (tid & 127);
    const int ih = (tid >> 7) * 32;

    float vv[64];
    #pragma unroll
    for (int j = 0; j < 64; j++) vv[j] = v[(long)j * N_ + n];

    #pragma unroll
    for (int ii = 0; ii < 32; ii++) {
        const float4* ar = (const float4*)&as[ih + ii][0];
        float acc = 0.0f;
        #pragma unroll
        for (int j4 = 0; j4 < 16; j4++) {
            float4 a4 = ar[j4];
            acc += a4.x * vv[j4 * 4 + 0] + a4.y * vv[j4 * 4 + 1]
                 + a4.z * vv[j4 * 4 + 2] + a4.w * vv[j4 * 4 + 3];
        }
        o[(long)(ih + ii) * N_ + n] = acc;
    }
}

// ============================================================================
// launch — kernel launches ONLY (no runtime API calls of any kind)
// ============================================================================
extern "C" void kernel_launch(void* const* d_in, const int* in_sizes, int n_in,
                              void* d_out, int out_size)
{
    const float* f_m  = (const float*)d_in[0];
    const float* f_n  = (const float*)d_in[1];
    const float* Wq   = (const float*)d_in[2];
    const float* Wkv  = (const float*)d_in[3];
    const float* Wout = (const float*)d_in[4];
    const float* bout = (const float*)d_in[5];
    float* out = (float*)d_out;

    const long sFM = (long)C_ * N_;       // f_m / f_n / q / o batch stride
    const long sKV = (long)2 * C_ * N_;   // kv batch stride

    // 1) q = Wq @ f_m          (B ext=f_m, C -> g_q)
    sgemm_kernel<<<dim3(N_ / 128, C_ / 128, B_), 256>>>(
        Wq, f_m, 0, nullptr, 1, nullptr, C_, N_, C_, sFM, sFM);

    // 2) kv = Wkv @ f_n        (B ext=f_n, C -> g_kv)
    sgemm_kernel<<<dim3(N_ / 128, (2 * C_) / 128, B_), 256>>>(
        Wkv, f_n, 0, nullptr, 2, nullptr, 2 * C_, N_, C_, sFM, sKV);

    // 3) dots + softmax
    scores_softmax_kernel<<<B_ * H_, 256>>>();

    // 4) o = attn @ v
    apply_v_kernel<<<dim3(N_ / 128, B_ * H_), 256>>>();

    // 5) out = Wout @ o + bout (B = g_o, C -> external out)
    sgemm_kernel<<<dim3(N_ / 128, C_ / 128, B_), 256>>>(
        Wout, nullptr, 3, out, 0, bout, C_, N_, C_, sFM, sFM);
}

// round 5
// speedup vs baseline: 2.1465x; 2.1465x over previous
#include <cuda_runtime.h>
#include <cstdint>

#define B_ 8
#define C_ 512
#define N_ 4096
#define H_ 8
#define D_ 64
#define K_ 512
#define SPLIT_ 8

// ---- scratch (device globals: allocation-free) ----
__device__ float g_fmT[(size_t)B_ * N_ * C_];        //  64 MB  [b][n][c]
__device__ float g_fnT[(size_t)B_ * N_ * C_];        //  64 MB
__device__ float g_qT [(size_t)B_ * N_ * C_];        //  64 MB  [b][n][c]
__device__ float g_kvT[(size_t)B_ * N_ * 2 * C_];    // 128 MB  [b][n][2c]
__device__ float g_oT [(size_t)B_ * N_ * C_];        //  64 MB
__device__ float g_attn[(size_t)B_ * H_ * D_ * D_];  //   1 MB
__device__ float g_part[(size_t)SPLIT_ * B_ * H_ * D_ * D_]; // 8 MB

__device__ __forceinline__ uint32_t tf32r(float x) {
    uint32_t u;
    asm("cvt.rna.tf32.f32 %0, %1;" : "=r"(u) : "f"(x));
    return u;
}

// m16n8k8 tf32 mma, fp32 accumulate (sm_80+ path, works on base sm_100)
__device__ __forceinline__ void mma_tf32(float* c, const uint32_t* a, const uint32_t* b) {
    asm volatile(
        "mma.sync.aligned.m16n8k8.row.col.f32.tf32.tf32.f32 "
        "{%0,%1,%2,%3}, {%4,%5,%6,%7}, {%8,%9}, {%0,%1,%2,%3};"
        : "+f"(c[0]), "+f"(c[1]), "+f"(c[2]), "+f"(c[3])
        : "r"(a[0]), "r"(a[1]), "r"(a[2]), "r"(a[3]), "r"(b[0]), "r"(b[1]));
}

// ---- buffer selectors (no cudaGetSymbolAddress needed) ----
__device__ __forceinline__ const float* rsel_c(int s, const float* e) {
    switch (s) {
        case 1: return g_fmT; case 2: return g_fnT; case 3: return g_qT;
        case 4: return g_kvT; case 5: return g_oT;  default: return e;
    }
}
__device__ __forceinline__ float* rsel(int s, float* e) {
    switch (s) {
        case 1: return g_fmT; case 2: return g_fnT; case 3: return g_qT;
        case 4: return g_kvT; case 5: return g_oT;  default: return e;
    }
}

// ============================================================================
// transpose: src [b][512][4096] -> dst [b][4096][512]
// ============================================================================
__global__ __launch_bounds__(256) void transpose_kernel(const float* __restrict__ src,
                                                        int dstSel)
{
    __shared__ float t[32][33];
    const int b  = blockIdx.z;
    const int n0 = blockIdx.x * 32;
    const int c0 = blockIdx.y * 32;
    const float* s = src + (long)b * C_ * N_;
    float*       d = rsel(dstSel, nullptr) + (long)b * N_ * C_;
    const int tx = threadIdx.x, ty = threadIdx.y;
    #pragma unroll
    for (int i = ty; i < 32; i += 8)
        t[i][tx] = s[(long)(c0 + i) * N_ + n0 + tx];
    __syncthreads();
    #pragma unroll
    for (int i = ty; i < 32; i += 8)
        d[(long)(n0 + i) * C_ + c0 + tx] = t[tx][i];
}

// ============================================================================
// tf32 tensor-core GEMM: D[m][n] = sum_k A[m][k] * B[n][k]   (K = 512)
// CTA tile 128x128x32, 8 warps (4M x 2N), warp tile 32x64, mma m16n8k8.
// SMEM stride 36 words -> fragment loads (4*row+col)%32 conflict-free.
// grid: (M/128, N/128, batch)
// ============================================================================
__global__ void __launch_bounds__(256) gemm_mma_kernel(
    const float* __restrict__ Aext, int aSel, long aStride,
    const float* __restrict__ Bext, int bSel, long bStride,
    float* __restrict__ Dext, int dSel, long dStride, int ldD,
    const float* __restrict__ bias)
{
    __shared__ uint32_t As[128][36];
    __shared__ uint32_t Bs[128][36];

    const int tid = threadIdx.x, lid = tid & 31, wid = tid >> 5;
    const int warpM = wid & 3;          // 0..3  (32-row slice)
    const int warpN = wid >> 2;         // 0..1  (64-col slice)
    const int m0 = blockIdx.x * 128;
    const int n0 = blockIdx.y * 128;
    const int bz = blockIdx.z;

    const float* A  = rsel_c(aSel, Aext) + (long)bz * aStride + (long)m0 * K_;
    const float* Bw = rsel_c(bSel, Bext) + (long)bz * bStride + (long)n0 * K_;
    float*       Dp = rsel(dSel, Dext)   + (long)bz * dStride;

    float acc[2][8][4] = {};

    for (int kt = 0; kt < 16; kt++) {
        const int k0 = kt * 32;
        // stage A,B tiles (128 x 32 fp32 each) with tf32 rounding
        #pragma unroll
        for (int l = 0; l < 4; l++) {
            int f = l * 256 + tid, row = f >> 3, q4 = f & 7;
            float4 va = *(const float4*)(A  + (long)row * K_ + k0 + q4 * 4);
            float4 vb = *(const float4*)(Bw + (long)row * K_ + k0 + q4 * 4);
            uint4 ta = { tf32r(va.x), tf32r(va.y), tf32r(va.z), tf32r(va.w) };
            uint4 tb = { tf32r(vb.x), tf32r(vb.y), tf32r(vb.z), tf32r(vb.w) };
            *(uint4*)&As[row][q4 * 4] = ta;
            *(uint4*)&Bs[row][q4 * 4] = tb;
        }
        __syncthreads();

        #pragma unroll
        for (int kk = 0; kk < 4; kk++) {
            const int cA = kk * 8 + (lid & 3);
            const int rA = warpM * 32 + (lid >> 2);
            uint32_t af[2][4];
            #pragma unroll
            for (int mt = 0; mt < 2; mt++) {
                af[mt][0] = As[rA + mt * 16 + 0][cA];
                af[mt][1] = As[rA + mt * 16 + 8][cA];
                af[mt][2] = As[rA + mt * 16 + 0][cA + 4];
                af[mt][3] = As[rA + mt * 16 + 8][cA + 4];
            }
            const int rB = warpN * 64 + (lid >> 2);
            uint32_t bf[8][2];
            #pragma unroll
            for (int nt = 0; nt < 8; nt++) {
                bf[nt][0] = Bs[rB + nt * 8][cA];
                bf[nt][1] = Bs[rB + nt * 8][cA + 4];
            }
            #pragma unroll
            for (int mt = 0; mt < 2; mt++)
                #pragma unroll
                for (int nt = 0; nt < 8; nt++)
                    mma_tf32(acc[mt][nt], af[mt], bf[nt]);
        }
        __syncthreads();
    }

    // epilogue: c0,c1 at (row, 2*(lid&3)+{0,1}); c2,c3 at row+8
    const int rowW = m0 + warpM * 32 + (lid >> 2);
    const int colW = n0 + warpN * 64 + 2 * (lid & 3);
    #pragma unroll
    for (int mt = 0; mt < 2; mt++) {
        const int r0 = rowW + mt * 16;
        const float bv0 = bias ? bias[r0] : 0.0f;
        const float bv1 = bias ? bias[r0 + 8] : 0.0f;
        #pragma unroll
        for (int nt = 0; nt < 8; nt++) {
            float2 lo = { acc[mt][nt][0] + bv0, acc[mt][nt][1] + bv0 };
            float2 hi = { acc[mt][nt][2] + bv1, acc[mt][nt][3] + bv1 };
            *(float2*)(Dp + (long)r0 * ldD + colW + nt * 8)       = lo;
            *(float2*)(Dp + (long)(r0 + 8) * ldD + colW + nt * 8) = hi;
        }
    }
}

// ============================================================================
// scores partial: part[s][bh][i][j] = sum_{n in slice s} qT[n][h64+i]*kvT[n][h64+j]
// grid (64 bh, SPLIT_), block 256
// ============================================================================
__global__ __launch_bounds__(256) void scores_partial_kernel()
{
    const int bh = blockIdx.x, s = blockIdx.y;
    const int b = bh >> 3, h = bh & 7;
    const float* q = g_qT  + (long)b * N_ * C_     + h * D_;
    const float* k = g_kvT + (long)b * N_ * 2 * C_ + h * D_;

    __shared__ float qs[64][68];
    __shared__ float ks[64][68];

    const int tid = threadIdx.x;
    const int i0  = (tid >> 4) * 4;
    const int j0  = (tid & 15) * 4;
    float acc[4][4] = {};

    const int nbeg = s * (N_ / SPLIT_);
    for (int n0 = nbeg; n0 < nbeg + N_ / SPLIT_; n0 += 64) {
        #pragma unroll
        for (int l = 0; l < 4; l++) {
            int f = tid + l * 256, r = f >> 4, c4 = f & 15;
            *(float4*)&qs[r][c4 * 4] = *(const float4*)(q + (long)(n0 + r) * C_ + c4 * 4);
            *(float4*)&ks[r][c4 * 4] = *(const float4*)(k + (long)(n0 + r) * 2 * C_ + c4 * 4);
        }
        __syncthreads();
        #pragma unroll 8
        for (int nn = 0; nn < 64; nn++) {
            float qa[4], ka[4];
            #pragma unroll
            for (int ii = 0; ii < 4; ii++) qa[ii] = qs[nn][i0 + ii];
            #pragma unroll
            for (int jj = 0; jj < 4; jj++) ka[jj] = ks[nn][j0 + jj];
            #pragma unroll
            for (int ii = 0; ii < 4; ii++)
                #pragma unroll
                for (int jj = 0; jj < 4; jj++)
                    acc[ii][jj] += qa[ii] * ka[jj];
        }
        __syncthreads();
    }
    float* out = g_part + ((long)s * 64 + bh) * (D_ * D_);
    #pragma unroll
    for (int ii = 0; ii < 4; ii++)
        #pragma unroll
        for (int jj = 0; jj < 4; jj++)
            out[(i0 + ii) * D_ + j0 + jj] = acc[ii][jj];
}

// ============================================================================
// softmax: sum partials, scale, row-softmax -> g_attn. grid 64, block 64.
// ============================================================================
__global__ __launch_bounds__(64) void softmax_kernel()
{
    const int bh = blockIdx.x, i = threadIdx.x;
    float row[64];
    #pragma unroll
    for (int j = 0; j < 64; j++) row[j] = 0.0f;
    for (int s = 0; s < SPLIT_; s++) {
        const float* p = g_part + ((long)s * 64 + bh) * (D_ * D_) + (long)i * D_;
        #pragma unroll
        for (int j = 0; j < 64; j++) row[j] += p[j];
    }
    float mx = -1e30f;
    #pragma unroll
    for (int j = 0; j < 64; j++) { row[j] *= 0.125f; mx = fmaxf(mx, row[j]); }
    float sum = 0.0f;
    #pragma unroll
    for (int j = 0; j < 64; j++) { row[j] = __expf(row[j] - mx); sum += row[j]; }
    const float inv = 1.0f / sum;
    float* out = g_attn + (long)bh * (D_ * D_) + (long)i * D_;
    #pragma unroll
    for (int j = 0; j < 64; j++) out[j] = row[j] * inv;
}

// ============================================================================
// apply_v: oT[n][h64+i] = sum_j attn[i][j] * kvT[n][C_+h64+j]
// grid (N_/256, 64 bh), block 256; thread owns one spatial n.
// ============================================================================
__global__ __launch_bounds__(256) void apply_v_kernel()
{
    const int bh = blockIdx.y;
    const int b = bh >> 3, h = bh & 7;
    __shared__ float as[64][64];
    const int tid = threadIdx.x;
    const float* attn = g_attn + (long)bh * (D_ * D_);
    #pragma unroll
    for (int l = 0; l < 4; l++) {
        int f = tid + l * 256;
        *(float4*)&as[f >> 4][(f & 15) * 4] = *(const float4*)(attn + f * 4);
    }
    __syncthreads();

    const long n = (long)blockIdx.x * 256 + tid;
    const float* v = g_kvT + (long)b * N_ * 2 * C_ + n * 2 * C_ + C_ + h * D_;

    float acc[64];
    #pragma unroll
    for (int i = 0; i < 64; i++) acc[i] = 0.0f;

    #pragma unroll
    for (int jc = 0; jc < 4; jc++) {
        float4 vv[4];
        #pragma unroll
        for (int t = 0; t < 4; t++) vv[t] = *(const float4*)(v + jc * 16 + t * 4);
        #pragma unroll
        for (int i = 0; i < 64; i++) {
            const float4* ar = (const float4*)&as[i][jc * 16];
            float4 a0 = ar[0], a1 = ar[1], a2 = ar[2], a3 = ar[3];
            acc[i] += a0.x * vv[0].x + a0.y * vv[0].y + a0.z * vv[0].z + a0.w * vv[0].w
                    + a1.x * vv[1].x + a1.y * vv[1].y + a1.z * vv[1].z + a1.w * vv[1].w
                    + a2.x * vv[2].x + a2.y * vv[2].y + a2.z * vv[2].z + a2.w * vv[2].w
                    + a3.x * vv[3].x + a3.y * vv[3].y + a3.z * vv[3].z + a3.w * vv[3].w;
        }
    }
    float* o = g_oT + (long)b * N_ * C_ + n * C_ + h * D_;
    #pragma unroll
    for (int j4 = 0; j4 < 16; j4++)
        *(float4*)(o + j4 * 4) = make_float4(acc[j4 * 4 + 0], acc[j4 * 4 + 1],
                                             acc[j4 * 4 + 2], acc[j4 * 4 + 3]);
}

// ============================================================================
// launch — kernel launches ONLY
// ============================================================================
extern "C" void kernel_launch(void* const* d_in, const int* in_sizes, int n_in,
                              void* d_out, int out_size)
{
    const float* f_m  = (const float*)d_in[0];
    const float* f_n  = (const float*)d_in[1];
    const float* Wq   = (const float*)d_in[2];
    const float* Wkv  = (const float*)d_in[3];
    const float* Wout = (const float*)d_in[4];
    const float* bout = (const float*)d_in[5];
    float* out = (float*)d_out;

    const long sT  = (long)N_ * C_;       // fmT/fnT/qT/oT batch stride
    const long sKV = (long)N_ * 2 * C_;   // kvT batch stride

    // 0) transpose inputs to spatial-major
    transpose_kernel<<<dim3(N_ / 32, C_ / 32, B_), dim3(32, 8)>>>(f_m, 1);
    transpose_kernel<<<dim3(N_ / 32, C_ / 32, B_), dim3(32, 8)>>>(f_n, 2);

    // 1) qT[n][c] = sum_k fmT[n][k] * Wq[c][k]
    gemm_mma_kernel<<<dim3(N_ / 128, C_ / 128, B_), 256>>>(
        nullptr, 1, sT, Wq, 0, 0, nullptr, 3, sT, C_, nullptr);

    // 2) kvT[n][c] = sum_k fnT[n][k] * Wkv[c][k]
    gemm_mma_kernel<<<dim3(N_ / 128, (2 * C_) / 128, B_), 256>>>(
        nullptr, 2, sT, Wkv, 0, 0, nullptr, 4, sKV, 2 * C_, nullptr);

    // 3) scores (split-K partials) + softmax
    scores_partial_kernel<<<dim3(B_ * H_, SPLIT_), 256>>>();
    softmax_kernel<<<B_ * H_, 64>>>();

    // 4) oT = attn @ v
    apply_v_kernel<<<dim3(N_ / 256, B_ * H_), 256>>>();

    // 5) out[c][n] = sum_k Wout[c][k] * oT[n][k] + bout[c]
    gemm_mma_kernel<<<dim3(C_ / 128, N_ / 128, B_), 256>>>(
        Wout, 0, 0, nullptr, 5, sT, out, 0, (long)C_ * N_, N_, bout);
}